// round 6
// baseline (speedup 1.0000x reference)
#include <cuda_runtime.h>

// input : 2 tensors float32 [2048, 8, 8, 64]  (re, im)   8,388,608 elems each
// output: float32 [2, 2048, 8, 16, 64]                  33,554,432 elems
//
// Per block b (qubit q = 0 if b even else 5; mask m = 32 or 1):
//   top (d 0..7):  out[i] = S * in[i ^ m],              S = 2^-0.25
//   bot (d 8..15): out_re[i] = sgn * A * (re[i]-im[i])
//                  out_im[i] = sgn * A * (re[i]+im[i]), A = 2^-0.75,
//                  sgn = (i & m) ? -1 : +1
//
// Part-split grid: CTAs in the first half of the grid produce ONLY the real
// part of the output; second half produce ONLY the imag part. Each half emits
// one contiguous 67 MB write stream (better DRAM page locality). Input is
// read twice, but it's L2-resident, and L2 had headroom.

#define S_CONST 0.8408964152537145f   // 2^-0.25
#define A_CONST 0.5946035575013605f   // 2^-0.75

__device__ __forceinline__ float4 scale4(float4 v, float s) {
    return make_float4(s * v.x, s * v.y, s * v.z, s * v.w);
}
__device__ __forceinline__ float4 swap_scale4(float4 v, float s) {
    return make_float4(s * v.y, s * v.x, s * v.w, s * v.z);
}
// c0*(a ± b) per lane with per-call uniform scale
__device__ __forceinline__ float4 axpy4(float4 a, float4 b, float s, float sb) {
    // returns s*a + sb*b  (sb = ±s encodes the re-im / re+im and sign)
    return make_float4(s * a.x + sb * b.x, s * a.y + sb * b.y,
                       s * a.z + sb * b.z, s * a.w + sb * b.w);
}

__global__ void __launch_bounds__(256)
entangle_split_kernel(const float4* __restrict__ re4,
                      const float4* __restrict__ im4,
                      float4* __restrict__ out4,
                      int n_pairs)   // 1,048,576 per part
{
    int gt = blockIdx.x * blockDim.x + threadIdx.x;
    int part = gt >= n_pairs;            // 0 = real part, 1 = imag part
    int t = part ? gt - n_pairs : gt;
    if (t >= n_pairs) return;

    // decode: t = ((bblk*8 + d)*8 + i8)
    int i8   = t & 7;           // low float4 index (0..7); partner at i8+8
    int rest = t >> 3;
    int d    = rest & 7;
    int bblk = rest >> 3;       // b*8 + blk
    int blk  = bblk & 7;
    const bool even_blk = (blk & 1) == 0;   // qubit 0 (m=32) vs qubit 5 (m=1)

    int f_lo = (bblk << 7) + (d << 4) + i8;
    int f_hi = f_lo + 8;

    float4 r_lo = re4[f_lo];
    float4 r_hi = re4[f_hi];
    float4 m_lo = im4[f_lo];
    float4 m_hi = im4[f_hi];

    // For part 0 (real): top = S*re[^mask]; bot = sgn*A*(re - im)
    // For part 1 (imag): top = S*im[^mask]; bot = sgn*A*(re + im)
    // Select the "primary" input for the top gate, and the bot combine sign.
    float4 p_lo = part ? m_lo : r_lo;    // primary (for top)
    float4 p_hi = part ? m_hi : r_hi;
    float bsign = part ? 1.0f : -1.0f;   // bot: re + bsign*im, then *sgn*A

    float4 t_lo, t_hi;    // top outputs (rows d)
    float4 b_lo, b_hi;    // bot outputs (rows d+8)

    if (even_blk) {
        // m=32: top is the cross half
        t_lo = scale4(p_hi, S_CONST);
        t_hi = scale4(p_lo, S_CONST);
        // bot sign: +A for lo half, -A for hi half
        b_lo = axpy4(r_lo, m_lo,  A_CONST,  A_CONST * bsign);
        b_hi = axpy4(r_hi, m_hi, -A_CONST, -A_CONST * bsign);
    } else {
        // m=1: top swaps adjacent lanes
        t_lo = swap_scale4(p_lo, S_CONST);
        t_hi = swap_scale4(p_hi, S_CONST);
        // bot sign alternates per lane: +,-,+,-
        float4 c_lo = axpy4(r_lo, m_lo, A_CONST, A_CONST * bsign);
        float4 c_hi = axpy4(r_hi, m_hi, A_CONST, A_CONST * bsign);
        b_lo = make_float4(c_lo.x, -c_lo.y, c_lo.z, -c_lo.w);
        b_hi = make_float4(c_hi.x, -c_hi.y, c_hi.z, -c_hi.w);
    }

    // output float4 layout: [2][2048][8][16][16f4]; part stride = PS4
    const int PS4 = 2048 * 8 * 16 * 16;             // 4,194,304
    int base = part ? PS4 : 0;
    int ot_lo = base + (bblk * 16 + d) * 16 + i8;   // top, lo float4
    int ot_hi = ot_lo + 8;
    int ob_lo = ot_lo + 8 * 16;                     // bot: row d+8
    int ob_hi = ob_lo + 8;

    out4[ot_lo] = t_lo;
    out4[ot_hi] = t_hi;
    out4[ob_lo] = b_lo;
    out4[ob_hi] = b_hi;
}

extern "C" void kernel_launch(void* const* d_in, const int* in_sizes, int n_in,
                              void* d_out, int out_size)
{
    const float4* re4 = (const float4*)d_in[0];
    const float4* im4 = (const float4*)d_in[1];
    float4* out4      = (float4*)d_out;

    int n_pairs = in_sizes[0] / 8;        // 1,048,576
    int total   = n_pairs * 2;            // one thread per (pair, part)
    int threads = 256;
    int blocks  = (total + threads - 1) / threads;   // 8192

    entangle_split_kernel<<<blocks, threads>>>(re4, im4, out4, n_pairs);
}

// round 7
// speedup vs baseline: 1.2693x; 1.2693x over previous
#include <cuda_runtime.h>
#include <cstdint>

// input : 2 tensors float32 [2048, 8, 8, 64]  (re, im)   8,388,608 elems each
// output: float32 [2, 2048, 8, 16, 64]                  33,554,432 elems
//
// Per block b (qubit q = 0 if b even else 5; mask m = 32 or 1):
//   top (d 0..7):  out[i] = S * in[i ^ m],              S = 2^-0.25
//   bot (d 8..15): out_re[i] = sgn * A * (re[i]-im[i])
//                  out_im[i] = sgn * A * (re[i]+im[i]), A = 2^-0.75,
//                  sgn = (i & m) ? -1 : +1
//
// Each thread owns the float4 pair {f, f^8}. Outputs are staged in SMEM and
// written with cp.async.bulk (TMA bulk store): per CTA, one 16KB contiguous
// burst for the real part and one for the imag part. Store path bypasses
// L1/LSU; DRAM sees maximal-locality bursts.

#define S_CONST 0.8408964152537145f   // 2^-0.25
#define A_CONST 0.5946035575013605f   // 2^-0.75

__device__ __forceinline__ float4 scale4(float4 v, float s) {
    return make_float4(s * v.x, s * v.y, s * v.z, s * v.w);
}
__device__ __forceinline__ float4 swap_scale4(float4 v, float s) {
    return make_float4(s * v.y, s * v.x, s * v.w, s * v.z);
}

__device__ __forceinline__ uint32_t smem_u32(const void* p) {
    return (uint32_t)__cvta_generic_to_shared(p);
}

__global__ void __launch_bounds__(256)
entangle_bulk_kernel(const float4* __restrict__ re4,
                     const float4* __restrict__ im4,
                     float* __restrict__ out,
                     int n_ctas)
{
    // SMEM images: [4 bblk][16 rows][16 float4] per part = 16KB each
    __shared__ float4 s_re[4 * 16 * 16];
    __shared__ float4 s_im[4 * 16 * 16];

    int cta = blockIdx.x;
    if (cta >= n_ctas) return;
    int tid = threadIdx.x;

    // decode within CTA: tid = ((bb_local*8 + d)*8 + i8)
    int i8  = tid & 7;            // low float4 index (0..7); partner at i8+8
    int d   = (tid >> 3) & 7;
    int bbl = (tid >> 6) & 3;     // local bblk 0..3
    int bblk = (cta << 2) + bbl;  // global b*8+blk
    int blk  = bblk & 7;
    const bool even_blk = (blk & 1) == 0;   // qubit 0 (m=32) vs qubit 5 (m=1)

    int f_lo = (bblk << 7) + (d << 4) + i8;
    int f_hi = f_lo + 8;

    float4 r_lo = re4[f_lo];
    float4 r_hi = re4[f_hi];
    float4 m_lo = im4[f_lo];
    float4 m_hi = im4[f_hi];

    float4 tr_lo, tr_hi, ti_lo, ti_hi;   // top (X gate)
    float4 br_lo, br_hi, bi_lo, bi_hi;   // bot (Z gate)

    if (even_blk) {
        tr_lo = scale4(r_hi, S_CONST);  ti_lo = scale4(m_hi, S_CONST);
        tr_hi = scale4(r_lo, S_CONST);  ti_hi = scale4(m_lo, S_CONST);
        br_lo = make_float4( A_CONST * (r_lo.x - m_lo.x),  A_CONST * (r_lo.y - m_lo.y),
                             A_CONST * (r_lo.z - m_lo.z),  A_CONST * (r_lo.w - m_lo.w));
        bi_lo = make_float4( A_CONST * (r_lo.x + m_lo.x),  A_CONST * (r_lo.y + m_lo.y),
                             A_CONST * (r_lo.z + m_lo.z),  A_CONST * (r_lo.w + m_lo.w));
        br_hi = make_float4(-A_CONST * (r_hi.x - m_hi.x), -A_CONST * (r_hi.y - m_hi.y),
                            -A_CONST * (r_hi.z - m_hi.z), -A_CONST * (r_hi.w - m_hi.w));
        bi_hi = make_float4(-A_CONST * (r_hi.x + m_hi.x), -A_CONST * (r_hi.y + m_hi.y),
                            -A_CONST * (r_hi.z + m_hi.z), -A_CONST * (r_hi.w + m_hi.w));
    } else {
        tr_lo = swap_scale4(r_lo, S_CONST);  ti_lo = swap_scale4(m_lo, S_CONST);
        tr_hi = swap_scale4(r_hi, S_CONST);  ti_hi = swap_scale4(m_hi, S_CONST);
        br_lo = make_float4( A_CONST * (r_lo.x - m_lo.x), -A_CONST * (r_lo.y - m_lo.y),
                             A_CONST * (r_lo.z - m_lo.z), -A_CONST * (r_lo.w - m_lo.w));
        bi_lo = make_float4( A_CONST * (r_lo.x + m_lo.x), -A_CONST * (r_lo.y + m_lo.y),
                             A_CONST * (r_lo.z + m_lo.z), -A_CONST * (r_lo.w + m_lo.w));
        br_hi = make_float4( A_CONST * (r_hi.x - m_hi.x), -A_CONST * (r_hi.y - m_hi.y),
                             A_CONST * (r_hi.z - m_hi.z), -A_CONST * (r_hi.w - m_hi.w));
        bi_hi = make_float4( A_CONST * (r_hi.x + m_hi.x), -A_CONST * (r_hi.y + m_hi.y),
                             A_CONST * (r_hi.z + m_hi.z), -A_CONST * (r_hi.w + m_hi.w));
    }

    // SMEM image layout mirrors gmem: [bbl][row 0..15][i4 0..15]
    int st = (bbl << 8) + (d << 4) + i8;    // top row d
    int sb = st + (8 << 4);                 // bot row d+8
    s_re[st]     = tr_lo;
    s_re[st + 8] = tr_hi;
    s_re[sb]     = br_lo;
    s_re[sb + 8] = br_hi;
    s_im[st]     = ti_lo;
    s_im[st + 8] = ti_hi;
    s_im[sb]     = bi_lo;
    s_im[sb + 8] = bi_hi;

    __syncthreads();
    asm volatile("fence.proxy.async.shared::cta;" ::: "memory");

    if (tid == 0) {
        const int PS = 2048 * 8 * 16 * 64;           // 16,777,216 floats
        float* g_re = out + (size_t)cta * 4096;      // 4 bblk * 16*64 floats
        float* g_im = g_re + PS;
        uint32_t sre = smem_u32(s_re);
        uint32_t sim = smem_u32(s_im);
        asm volatile("cp.async.bulk.global.shared::cta.bulk_group [%0], [%1], %2;"
                     :: "l"(g_re), "r"(sre), "n"(16384) : "memory");
        asm volatile("cp.async.bulk.global.shared::cta.bulk_group [%0], [%1], %2;"
                     :: "l"(g_im), "r"(sim), "n"(16384) : "memory");
        asm volatile("cp.async.bulk.commit_group;" ::: "memory");
        asm volatile("cp.async.bulk.wait_group 0;" ::: "memory");
    }
}

extern "C" void kernel_launch(void* const* d_in, const int* in_sizes, int n_in,
                              void* d_out, int out_size)
{
    const float4* re4 = (const float4*)d_in[0];
    const float4* im4 = (const float4*)d_in[1];
    float* out        = (float*)d_out;

    int n_pairs = in_sizes[0] / 8;        // 1,048,576
    int n_ctas  = n_pairs / 256;          // 4096
    entangle_bulk_kernel<<<n_ctas, 256>>>(re4, im4, out, n_ctas);
}